// round 14
// baseline (speedup 1.0000x reference)
#include <cuda_runtime.h>
#include <math.h>

// ---------------- problem constants ----------------
#define BB    32
#define TT    128
#define TENC  128
#define UU    64
#define G4    256     // 4*U
#define EE    512
#define VV    32000
#define BT    4096    // B*T
#define OUT_ELEMS (BT * VV)   // 131,072,000
#define TAIL_ELEMS (2 * BB * UU)  // hT + cT = 4096

// ---------------- scratch (__device__ globals; no runtime alloc) ----------
__device__ float g_xz[BT * G4];       // [bt][4U]  input gate pre-activations
__device__ float g_feat[BT * 128];    // [bt][0:64]=h_t, [64:128]=ctx
__device__ float g_partial[256 * BT]; // [block][row] partial exp sums (250 blocks used)
__device__ float g_rowinv[BT];        // 1 / rowsum
__device__ float g_tail_sink[TAIL_ELEMS]; // fallback if d_out has no tail space

// ============================================================
// K1: xz[bt][g] = emb[tok[bt]] . Wx[:,g] + b[g]
// M=4096 N=256 K=512; BM=64 BN=64 BK=16; 256 thr; 4x4 micro
// ============================================================
#define K1_BM 64
#define K1_BN 64
#define K1_BK 16
__global__ void __launch_bounds__(256) k1_embed_gemm(
    const int* __restrict__ tok, const float* __restrict__ emb,
    const float* __restrict__ Wx, const float* __restrict__ bias)
{
    __shared__ float sX[K1_BK][K1_BM + 1];  // [k][m], padded
    __shared__ float sW[K1_BK][K1_BN];      // [k][n]
    __shared__ int   sTok[K1_BM];

    int tid = threadIdx.x;
    int tx = tid & 15, ty = tid >> 4;
    int m0 = blockIdx.y * K1_BM;
    int n0 = blockIdx.x * K1_BN;

    if (tid < K1_BM) sTok[tid] = tok[m0 + tid];
    __syncthreads();

    float acc[4][4] = {};
    for (int k0 = 0; k0 < EE; k0 += K1_BK) {
        #pragma unroll
        for (int i = 0; i < 4; i++) {
            int idx = tid + i * 256;           // 1024 elems of X
            int m = idx >> 4, k = idx & 15;
            sX[k][m] = emb[(long)sTok[m] * EE + k0 + k];
        }
        #pragma unroll
        for (int i = 0; i < 4; i++) {
            int idx = tid + i * 256;           // 1024 elems of W
            int k = idx >> 6, n = idx & 63;
            sW[k][n] = Wx[(k0 + k) * G4 + n0 + n];
        }
        __syncthreads();
        #pragma unroll
        for (int k = 0; k < K1_BK; k++) {
            float a[4], w[4];
            #pragma unroll
            for (int i = 0; i < 4; i++) a[i] = sX[k][ty * 4 + i];
            #pragma unroll
            for (int j = 0; j < 4; j++) w[j] = sW[k][tx * 4 + j];
            #pragma unroll
            for (int i = 0; i < 4; i++)
                #pragma unroll
                for (int j = 0; j < 4; j++) acc[i][j] += a[i] * w[j];
        }
        __syncthreads();
    }
    #pragma unroll
    for (int i = 0; i < 4; i++)
        #pragma unroll
        for (int j = 0; j < 4; j++) {
            int n = n0 + tx * 4 + j;
            g_xz[(m0 + ty * 4 + i) * G4 + n] = acc[i][j] + bias[n];
        }
}

// ============================================================
// K2: LSTM scan. One block per batch element (batch-parallel).
// 256 threads: thread g owns gate column g (Wh column in regs).
// Writes h_t into g_feat[bt][0:64]; final (hT,cT) to out_tail.
// ============================================================
__global__ void __launch_bounds__(256) k2_lstm(
    const float* __restrict__ h0, const float* __restrict__ c0,
    const float* __restrict__ Wh, float* __restrict__ out_tail)
{
    int b = blockIdx.x;
    int g = threadIdx.x;

    __shared__ float h_sh[UU];
    __shared__ float c_sh[UU];
    __shared__ float z_sh[G4];

    float whr[UU];
    #pragma unroll
    for (int k = 0; k < UU; k++) whr[k] = Wh[k * G4 + g];

    if (g < UU) { h_sh[g] = h0[b * UU + g]; c_sh[g] = c0[b * UU + g]; }
    __syncthreads();

    for (int t = 0; t < TT; t++) {
        int bt = b * TT + t;
        float z = g_xz[bt * G4 + g];
        #pragma unroll
        for (int k = 0; k < UU; k++) z += h_sh[k] * whr[k];
        z_sh[g] = z;
        __syncthreads();
        if (g < UU) {
            float zi = z_sh[g], zf = z_sh[UU + g], zg = z_sh[2 * UU + g], zo = z_sh[3 * UU + g];
            float ig = 1.f / (1.f + expf(-zi));
            float fg = 1.f / (1.f + expf(-zf));
            float og = 1.f / (1.f + expf(-zo));
            float cn = fg * c_sh[g] + ig * tanhf(zg);
            float hn = og * tanhf(cn);
            c_sh[g] = cn;
            h_sh[g] = hn;
            g_feat[bt * 128 + g] = hn;
        }
        __syncthreads();
    }
    if (g < UU) {
        out_tail[b * UU + g]            = h_sh[g];   // hT
        out_tail[BB * UU + b * UU + g]  = c_sh[g];   // cT
    }
}

// ============================================================
// K3: Luong attention per (b,t). query = h_{t-1} (h0 at t=0).
// scores over 128 enc positions, softmax, ctx -> g_feat[bt][64:128]
// ============================================================
__global__ void __launch_bounds__(128) k3_attn(
    const float* __restrict__ enc, const float* __restrict__ h0)
{
    int bt = blockIdx.x;
    int b = bt >> 7, t = bt & 127;
    int tid = threadIdx.x;

    __shared__ float sEnc[TENC * 65];  // [s][u] padded stride 65
    __shared__ float q[UU];
    __shared__ float attn[TENC];
    __shared__ float tmp[TENC];

    for (int i = tid; i < TENC * UU; i += 128) {
        int s = i >> 6, u = i & 63;
        sEnc[s * 65 + u] = enc[(b * TENC + s) * UU + u];
    }
    if (tid < UU)
        q[tid] = (t == 0) ? h0[b * UU + tid] : g_feat[(bt - 1) * 128 + tid];
    __syncthreads();

    int s = tid;
    float sc = 0.f;
    #pragma unroll
    for (int u = 0; u < UU; u++) sc += q[u] * sEnc[s * 65 + u];

    // block max
    tmp[tid] = sc; __syncthreads();
    #pragma unroll
    for (int off = 64; off >= 1; off >>= 1) {
        if (tid < off) tmp[tid] = fmaxf(tmp[tid], tmp[tid + off]);
        __syncthreads();
    }
    float mx = tmp[0]; __syncthreads();

    float e = expf(sc - mx);
    attn[tid] = e;
    tmp[tid] = e; __syncthreads();
    #pragma unroll
    for (int off = 64; off >= 1; off >>= 1) {
        if (tid < off) tmp[tid] += tmp[tid + off];
        __syncthreads();
    }
    float inv = 1.f / tmp[0];
    __syncthreads();
    attn[tid] *= inv;
    __syncthreads();

    if (tid < UU) {
        int u = tid;
        float c = 0.f;
        #pragma unroll 8
        for (int ss = 0; ss < TENC; ss++) c += attn[ss] * sEnc[ss * 65 + u];
        g_feat[bt * 128 + 64 + u] = c;
    }
}

// ============================================================
// K4: out = exp(feat @ Wd + bd), per-row partial sums (deterministic).
// M=4096 N=32000 K=128. Block tile 128x128, BK=32 (static smem 32KB).
// 256 thr: tx=tid&31 -> 4 cols each (LDS.128 of B conflict-free),
// wy=tid>>5 -> 16 rows each (A reads warp-broadcast).
// Packed fma.rn.f32x2: 2 fp32 MACs / instr. fma-pipe bound.
// ============================================================
#define BM4 128
#define BN4 128
#define BK4 32
__global__ void __launch_bounds__(256) k4_gemm_exp(
    const float* __restrict__ Wd, const float* __restrict__ bd,
    float* __restrict__ out)
{
    __shared__ float sF[BM4 * BK4];   // [m][k] stride 32
    __shared__ float sW[BK4 * BN4];   // [k][n] stride 128

    int tid = threadIdx.x;
    int tx = tid & 31;        // n: 4 cols each
    int wy = tid >> 5;        // m: 16 rows each
    int m0 = blockIdx.y * BM4;
    int n0 = blockIdx.x * BN4;

    unsigned long long acc[16][2];
    #pragma unroll
    for (int r = 0; r < 16; r++) { acc[r][0] = 0ULL; acc[r][1] = 0ULL; }

    #pragma unroll
    for (int kc = 0; kc < 128; kc += BK4) {
        // load feat tile: 128m x 32k = 1024 float4
        #pragma unroll
        for (int i = 0; i < 4; i++) {
            int idx4 = tid + i * 256;
            int m = idx4 >> 3, k4 = (idx4 & 7) * 4;
            *(float4*)(sF + m * BK4 + k4) =
                *(const float4*)(g_feat + (m0 + m) * 128 + kc + k4);
        }
        // load Wd tile: 32k x 128n = 1024 float4
        #pragma unroll
        for (int i = 0; i < 4; i++) {
            int idx4 = tid + i * 256;
            int k = idx4 >> 5, n4 = (idx4 & 31) * 4;
            *(float4*)(sW + k * BN4 + n4) =
                *(const float4*)(Wd + (long)(kc + k) * VV + n0 + n4);
        }
        __syncthreads();

        #pragma unroll
        for (int k0 = 0; k0 < BK4; k0 += 4) {
            ulonglong2 bv[4];
            #pragma unroll
            for (int kk = 0; kk < 4; kk++)
                bv[kk] = *(const ulonglong2*)(sW + (k0 + kk) * BN4 + tx * 4);
            #pragma unroll
            for (int r = 0; r < 16; r++) {
                float4 a4 = *(const float4*)(sF + (wy * 16 + r) * BK4 + k0);
                float av;
                unsigned long long ap;
                #pragma unroll
                for (int kk = 0; kk < 4; kk++) {
                    av = (kk == 0) ? a4.x : (kk == 1) ? a4.y
                       : (kk == 2) ? a4.z : a4.w;
                    asm("mov.b64 %0, {%1, %1};" : "=l"(ap) : "r"(__float_as_uint(av)));
                    asm("fma.rn.f32x2 %0, %1, %2, %0;"
                        : "+l"(acc[r][0]) : "l"(ap), "l"(bv[kk].x));
                    asm("fma.rn.f32x2 %0, %1, %2, %0;"
                        : "+l"(acc[r][1]) : "l"(ap), "l"(bv[kk].y));
                }
            }
        }
        __syncthreads();
    }

    // epilogue: + bd, exp, store, warp-reduced per-row partial sums
    float4 bdv = *(const float4*)(bd + n0 + tx * 4);

    #pragma unroll
    for (int r = 0; r < 16; r++) {
        unsigned u0, u1, u2, u3;
        asm("mov.b64 {%0, %1}, %2;" : "=r"(u0), "=r"(u1) : "l"(acc[r][0]));
        asm("mov.b64 {%0, %1}, %2;" : "=r"(u2), "=r"(u3) : "l"(acc[r][1]));
        float v0 = __expf(__uint_as_float(u0) + bdv.x);
        float v1 = __expf(__uint_as_float(u1) + bdv.y);
        float v2 = __expf(__uint_as_float(u2) + bdv.z);
        float v3 = __expf(__uint_as_float(u3) + bdv.w);

        int row = m0 + wy * 16 + r;
        *(float4*)(out + (long)row * VV + n0 + tx * 4) =
            make_float4(v0, v1, v2, v3);

        float s = (v0 + v1) + (v2 + v3);
        #pragma unroll
        for (int off = 16; off >= 1; off >>= 1)
            s += __shfl_down_sync(0xFFFFFFFFu, s, off);
        if (tx == 0)
            g_partial[blockIdx.x * BT + row] = s;   // [block][row]: K5a coalesced
    }
}

// ============================================================
// K5a: rowinv = 1 / sum of 250 partials (deterministic order,
// coalesced reads: fixed j across threads is contiguous in row)
// ============================================================
__global__ void k5a_rowsum() {
    int r = blockIdx.x * 256 + threadIdx.x;
    if (r < BT) {
        float s = 0.f;
        for (int j = 0; j < 250; j++) s += g_partial[j * BT + r];
        g_rowinv[r] = 1.f / s;
    }
}

// ============================================================
// K5: normalize out in place (float4)
// ============================================================
__global__ void __launch_bounds__(256) k5_norm(float* __restrict__ out) {
    int row = blockIdx.y;
    int c4 = blockIdx.x * 256 + threadIdx.x;
    if (c4 < VV / 4) {
        float inv = g_rowinv[row];
        float4* p = (float4*)(out + (long)row * VV) + c4;
        float4 v = *p;
        v.x *= inv; v.y *= inv; v.z *= inv; v.w *= inv;
        *p = v;
    }
}

// ============================================================
// Host: resolve inputs by unique element count (robust to any
// metadata ordering). h0/c0 share size 2048 -> encounter order.
// Tail (hT,cT) written to d_out only if out_size has room.
// ============================================================
extern "C" void kernel_launch(void* const* d_in, const int* in_sizes, int n_in,
                              void* d_out, int out_size)
{
    const float* enc  = 0;   // 262144
    const int*   tok  = 0;   // 4096
    const float* h0   = 0;   // 2048 (first)
    const float* c0   = 0;   // 2048 (second)
    const float* emb  = 0;   // 16384000
    const float* Wx   = 0;   // 131072
    const float* Wh   = 0;   // 16384
    const float* bias = 0;   // 256
    const float* Wd   = 0;   // 4096000
    const float* bd   = 0;   // 32000

    for (int i = 0; i < n_in; i++) {
        int sz = in_sizes[i];
        const void* p = d_in[i];
        switch (sz) {
            case BB * TENC * UU:  enc  = (const float*)p; break;  // 262144
            case BT:              tok  = (const int*)p;   break;  // 4096
            case 16384000:        emb  = (const float*)p; break;  // VOCAB*EMBED
            case EE * G4:         Wx   = (const float*)p; break;  // 131072
            case UU * G4:         Wh   = (const float*)p; break;  // 16384
            case G4:              bias = (const float*)p; break;  // 256
            case 4096000:         Wd   = (const float*)p; break;  // 2U*VOCAB
            case VV:              bd   = (const float*)p; break;  // 32000
            case BB * UU:                                          // 2048 x2
                if (!h0) h0 = (const float*)p; else c0 = (const float*)p;
                break;
            default: break;
        }
    }
    float* out = (float*)d_out;

    // tail target: d_out tail if the harness allocated room, else scratch
    float* tail;
    if ((long)out_size >= (long)OUT_ELEMS + TAIL_ELEMS) {
        tail = out + (long)OUT_ELEMS;
    } else {
        cudaGetSymbolAddress((void**)&tail, g_tail_sink);
    }

    // K1: embed + input GEMM
    k1_embed_gemm<<<dim3(G4 / K1_BN, BT / K1_BM), 256>>>(tok, emb, Wx, bias);
    // K2: LSTM scan (writes h_t into feat[:, :64] and hT/cT to tail)
    k2_lstm<<<BB, 256>>>(h0, c0, Wh, tail);
    // K3: attention (writes ctx into feat[:, 64:])
    k3_attn<<<BT, 128>>>(enc, h0);
    // K4: logits GEMM + exp + partial sums
    k4_gemm_exp<<<dim3(VV / BN4, BT / BM4), 256>>>(Wd, bd, out);
    // K5a: row sums -> reciprocals
    k5a_rowsum<<<(BT + 255) / 256, 256>>>();
    // K5: normalize
    k5_norm<<<dim3(32, BT), 256>>>(out);
}

// round 15
// speedup vs baseline: 1.0808x; 1.0808x over previous
#include <cuda_runtime.h>
#include <math.h>

// ---------------- problem constants ----------------
#define BB    32
#define TT    128
#define TENC  128
#define UU    64
#define G4    256     // 4*U
#define EE    512
#define VV    32000
#define BT    4096    // B*T
#define OUT_ELEMS (BT * VV)   // 131,072,000
#define TAIL_ELEMS (2 * BB * UU)  // hT + cT = 4096

// ---------------- scratch (__device__ globals; no runtime alloc) ----------
__device__ float g_xz[BT * G4];       // [bt][4U]  input gate pre-activations
__device__ float g_feat[BT * 128];    // [bt][0:64]=h_t, [64:128]=ctx
__device__ float g_partial[256 * BT]; // [block][row] partial exp sums (250 blocks used)
__device__ float g_rowinv[BT];        // 1 / rowsum
__device__ float g_tail_sink[TAIL_ELEMS]; // fallback if d_out has no tail space

// ============================================================
// K1: xz[bt][g] = emb[tok[bt]] . Wx[:,g] + b[g]
// ============================================================
#define K1_BM 64
#define K1_BN 64
#define K1_BK 16
__global__ void __launch_bounds__(256) k1_embed_gemm(
    const int* __restrict__ tok, const float* __restrict__ emb,
    const float* __restrict__ Wx, const float* __restrict__ bias)
{
    __shared__ float sX[K1_BK][K1_BM + 1];  // [k][m], padded
    __shared__ float sW[K1_BK][K1_BN];      // [k][n]
    __shared__ int   sTok[K1_BM];

    int tid = threadIdx.x;
    int tx = tid & 15, ty = tid >> 4;
    int m0 = blockIdx.y * K1_BM;
    int n0 = blockIdx.x * K1_BN;

    if (tid < K1_BM) sTok[tid] = tok[m0 + tid];
    __syncthreads();

    float acc[4][4] = {};
    for (int k0 = 0; k0 < EE; k0 += K1_BK) {
        #pragma unroll
        for (int i = 0; i < 4; i++) {
            int idx = tid + i * 256;
            int m = idx >> 4, k = idx & 15;
            sX[k][m] = emb[(long)sTok[m] * EE + k0 + k];
        }
        #pragma unroll
        for (int i = 0; i < 4; i++) {
            int idx = tid + i * 256;
            int k = idx >> 6, n = idx & 63;
            sW[k][n] = Wx[(k0 + k) * G4 + n0 + n];
        }
        __syncthreads();
        #pragma unroll
        for (int k = 0; k < K1_BK; k++) {
            float a[4], w[4];
            #pragma unroll
            for (int i = 0; i < 4; i++) a[i] = sX[k][ty * 4 + i];
            #pragma unroll
            for (int j = 0; j < 4; j++) w[j] = sW[k][tx * 4 + j];
            #pragma unroll
            for (int i = 0; i < 4; i++)
                #pragma unroll
                for (int j = 0; j < 4; j++) acc[i][j] += a[i] * w[j];
        }
        __syncthreads();
    }
    #pragma unroll
    for (int i = 0; i < 4; i++)
        #pragma unroll
        for (int j = 0; j < 4; j++) {
            int n = n0 + tx * 4 + j;
            g_xz[(m0 + ty * 4 + i) * G4 + n] = acc[i][j] + bias[n];
        }
}

// ============================================================
// K2: LSTM scan. One block per batch element (batch-parallel).
// ============================================================
__global__ void __launch_bounds__(256) k2_lstm(
    const float* __restrict__ h0, const float* __restrict__ c0,
    const float* __restrict__ Wh, float* __restrict__ out_tail)
{
    int b = blockIdx.x;
    int g = threadIdx.x;

    __shared__ float h_sh[UU];
    __shared__ float c_sh[UU];
    __shared__ float z_sh[G4];

    float whr[UU];
    #pragma unroll
    for (int k = 0; k < UU; k++) whr[k] = Wh[k * G4 + g];

    if (g < UU) { h_sh[g] = h0[b * UU + g]; c_sh[g] = c0[b * UU + g]; }
    __syncthreads();

    for (int t = 0; t < TT; t++) {
        int bt = b * TT + t;
        float z = g_xz[bt * G4 + g];
        #pragma unroll
        for (int k = 0; k < UU; k++) z += h_sh[k] * whr[k];
        z_sh[g] = z;
        __syncthreads();
        if (g < UU) {
            float zi = z_sh[g], zf = z_sh[UU + g], zg = z_sh[2 * UU + g], zo = z_sh[3 * UU + g];
            float ig = 1.f / (1.f + expf(-zi));
            float fg = 1.f / (1.f + expf(-zf));
            float og = 1.f / (1.f + expf(-zo));
            float cn = fg * c_sh[g] + ig * tanhf(zg);
            float hn = og * tanhf(cn);
            c_sh[g] = cn;
            h_sh[g] = hn;
            g_feat[bt * 128 + g] = hn;
        }
        __syncthreads();
    }
    if (g < UU) {
        out_tail[b * UU + g]            = h_sh[g];   // hT
        out_tail[BB * UU + b * UU + g]  = c_sh[g];   // cT
    }
}

// ============================================================
// K3: Luong attention per (b,t). query = h_{t-1} (h0 at t=0).
// ============================================================
__global__ void __launch_bounds__(128) k3_attn(
    const float* __restrict__ enc, const float* __restrict__ h0)
{
    int bt = blockIdx.x;
    int b = bt >> 7, t = bt & 127;
    int tid = threadIdx.x;

    __shared__ float sEnc[TENC * 65];  // [s][u] padded stride 65
    __shared__ float q[UU];
    __shared__ float attn[TENC];
    __shared__ float tmp[TENC];

    for (int i = tid; i < TENC * UU; i += 128) {
        int s = i >> 6, u = i & 63;
        sEnc[s * 65 + u] = enc[(b * TENC + s) * UU + u];
    }
    if (tid < UU)
        q[tid] = (t == 0) ? h0[b * UU + tid] : g_feat[(bt - 1) * 128 + tid];
    __syncthreads();

    int s = tid;
    float sc = 0.f;
    #pragma unroll
    for (int u = 0; u < UU; u++) sc += q[u] * sEnc[s * 65 + u];

    tmp[tid] = sc; __syncthreads();
    #pragma unroll
    for (int off = 64; off >= 1; off >>= 1) {
        if (tid < off) tmp[tid] = fmaxf(tmp[tid], tmp[tid + off]);
        __syncthreads();
    }
    float mx = tmp[0]; __syncthreads();

    float e = expf(sc - mx);
    attn[tid] = e;
    tmp[tid] = e; __syncthreads();
    #pragma unroll
    for (int off = 64; off >= 1; off >>= 1) {
        if (tid < off) tmp[tid] += tmp[tid + off];
        __syncthreads();
    }
    float inv = 1.f / tmp[0];
    __syncthreads();
    attn[tid] *= inv;
    __syncthreads();

    if (tid < UU) {
        int u = tid;
        float c = 0.f;
        #pragma unroll 8
        for (int ss = 0; ss < TENC; ss++) c += attn[ss] * sEnc[ss * 65 + u];
        g_feat[bt * 128 + 64 + u] = c;
    }
}

// ============================================================
// K4: out = exp(feat @ Wd + bd), per-row partial sums (deterministic).
// M=4096 N=32000 K=128. Block tile 64x128 (BM halved vs R14 to cut
// regs 158 -> <=128 and double occupancy to 2 blocks/SM), BK=32.
// 256 thr: tx=tid&31 -> 4 cols (LDS.128 of B conflict-free),
// wy=tid>>5 -> 8 rows each (A reads warp-broadcast).
// Packed fma.rn.f32x2: 2 fp32 MACs / instr.
// ============================================================
#define BM4 64
#define BN4 128
#define BK4 32
__global__ void __launch_bounds__(256, 2) k4_gemm_exp(
    const float* __restrict__ Wd, const float* __restrict__ bd,
    float* __restrict__ out)
{
    __shared__ float sF[BM4 * BK4];   // [m][k] stride 32 (8 KB)
    __shared__ float sW[BK4 * BN4];   // [k][n] stride 128 (16 KB)

    int tid = threadIdx.x;
    int tx = tid & 31;        // n: 4 cols each
    int wy = tid >> 5;        // m: 8 rows each
    int m0 = blockIdx.y * BM4;
    int n0 = blockIdx.x * BN4;

    unsigned long long acc[8][2];
    #pragma unroll
    for (int r = 0; r < 8; r++) { acc[r][0] = 0ULL; acc[r][1] = 0ULL; }

    #pragma unroll
    for (int kc = 0; kc < 128; kc += BK4) {
        // load feat tile: 64m x 32k = 512 float4 (2 per thread)
        #pragma unroll
        for (int i = 0; i < 2; i++) {
            int idx4 = tid + i * 256;
            int m = idx4 >> 3, k4 = (idx4 & 7) * 4;
            *(float4*)(sF + m * BK4 + k4) =
                *(const float4*)(g_feat + (m0 + m) * 128 + kc + k4);
        }
        // load Wd tile: 32k x 128n = 1024 float4 (4 per thread)
        #pragma unroll
        for (int i = 0; i < 4; i++) {
            int idx4 = tid + i * 256;
            int k = idx4 >> 5, n4 = (idx4 & 31) * 4;
            *(float4*)(sW + k * BN4 + n4) =
                *(const float4*)(Wd + (long)(kc + k) * VV + n0 + n4);
        }
        __syncthreads();

        #pragma unroll
        for (int k0 = 0; k0 < BK4; k0 += 4) {
            ulonglong2 bv[4];
            #pragma unroll
            for (int kk = 0; kk < 4; kk++)
                bv[kk] = *(const ulonglong2*)(sW + (k0 + kk) * BN4 + tx * 4);
            #pragma unroll
            for (int r = 0; r < 8; r++) {
                float4 a4 = *(const float4*)(sF + (wy * 8 + r) * BK4 + k0);
                float av;
                unsigned long long ap;
                #pragma unroll
                for (int kk = 0; kk < 4; kk++) {
                    av = (kk == 0) ? a4.x : (kk == 1) ? a4.y
                       : (kk == 2) ? a4.z : a4.w;
                    asm("mov.b64 %0, {%1, %1};" : "=l"(ap) : "r"(__float_as_uint(av)));
                    asm("fma.rn.f32x2 %0, %1, %2, %0;"
                        : "+l"(acc[r][0]) : "l"(ap), "l"(bv[kk].x));
                    asm("fma.rn.f32x2 %0, %1, %2, %0;"
                        : "+l"(acc[r][1]) : "l"(ap), "l"(bv[kk].y));
                }
            }
        }
        __syncthreads();
    }

    // epilogue: + bd, exp, store, warp-reduced per-row partial sums
    float4 bdv = *(const float4*)(bd + n0 + tx * 4);

    #pragma unroll
    for (int r = 0; r < 8; r++) {
        unsigned u0, u1, u2, u3;
        asm("mov.b64 {%0, %1}, %2;" : "=r"(u0), "=r"(u1) : "l"(acc[r][0]));
        asm("mov.b64 {%0, %1}, %2;" : "=r"(u2), "=r"(u3) : "l"(acc[r][1]));
        float v0 = __expf(__uint_as_float(u0) + bdv.x);
        float v1 = __expf(__uint_as_float(u1) + bdv.y);
        float v2 = __expf(__uint_as_float(u2) + bdv.z);
        float v3 = __expf(__uint_as_float(u3) + bdv.w);

        int row = m0 + wy * 8 + r;
        *(float4*)(out + (long)row * VV + n0 + tx * 4) =
            make_float4(v0, v1, v2, v3);

        float s = (v0 + v1) + (v2 + v3);
        #pragma unroll
        for (int off = 16; off >= 1; off >>= 1)
            s += __shfl_down_sync(0xFFFFFFFFu, s, off);
        if (tx == 0)
            g_partial[blockIdx.x * BT + row] = s;   // [block][row]: K5a coalesced
    }
}

// ============================================================
// K5a: rowinv = 1 / sum of 250 partials (deterministic, coalesced)
// ============================================================
__global__ void k5a_rowsum() {
    int r = blockIdx.x * 256 + threadIdx.x;
    if (r < BT) {
        float s = 0.f;
        for (int j = 0; j < 250; j++) s += g_partial[j * BT + r];
        g_rowinv[r] = 1.f / s;
    }
}

// ============================================================
// K5: normalize out in place (float4)
// ============================================================
__global__ void __launch_bounds__(256) k5_norm(float* __restrict__ out) {
    int row = blockIdx.y;
    int c4 = blockIdx.x * 256 + threadIdx.x;
    if (c4 < VV / 4) {
        float inv = g_rowinv[row];
        float4* p = (float4*)(out + (long)row * VV) + c4;
        float4 v = *p;
        v.x *= inv; v.y *= inv; v.z *= inv; v.w *= inv;
        *p = v;
    }
}

// ============================================================
// Host: resolve inputs by unique element count; bounds-safe tail.
// ============================================================
extern "C" void kernel_launch(void* const* d_in, const int* in_sizes, int n_in,
                              void* d_out, int out_size)
{
    const float* enc  = 0;   // 262144
    const int*   tok  = 0;   // 4096
    const float* h0   = 0;   // 2048 (first)
    const float* c0   = 0;   // 2048 (second)
    const float* emb  = 0;   // 16384000
    const float* Wx   = 0;   // 131072
    const float* Wh   = 0;   // 16384
    const float* bias = 0;   // 256
    const float* Wd   = 0;   // 4096000
    const float* bd   = 0;   // 32000

    for (int i = 0; i < n_in; i++) {
        int sz = in_sizes[i];
        const void* p = d_in[i];
        switch (sz) {
            case BB * TENC * UU:  enc  = (const float*)p; break;
            case BT:              tok  = (const int*)p;   break;
            case 16384000:        emb  = (const float*)p; break;
            case EE * G4:         Wx   = (const float*)p; break;
            case UU * G4:         Wh   = (const float*)p; break;
            case G4:              bias = (const float*)p; break;
            case 4096000:         Wd   = (const float*)p; break;
            case VV:              bd   = (const float*)p; break;
            case BB * UU:
                if (!h0) h0 = (const float*)p; else c0 = (const float*)p;
                break;
            default: break;
        }
    }
    float* out = (float*)d_out;

    float* tail;
    if ((long)out_size >= (long)OUT_ELEMS + TAIL_ELEMS) {
        tail = out + (long)OUT_ELEMS;
    } else {
        cudaGetSymbolAddress((void**)&tail, g_tail_sink);
    }

    // K1: embed + input GEMM
    k1_embed_gemm<<<dim3(G4 / K1_BN, BT / K1_BM), 256>>>(tok, emb, Wx, bias);
    // K2: LSTM scan
    k2_lstm<<<BB, 256>>>(h0, c0, Wh, tail);
    // K3: attention
    k3_attn<<<BT, 128>>>(enc, h0);
    // K4: logits GEMM + exp + partial sums (BM=64 -> 16000 blocks)
    k4_gemm_exp<<<dim3(VV / BN4, BT / BM4), 256>>>(Wd, bd, out);
    // K5a: row sums -> reciprocals
    k5a_rowsum<<<(BT + 255) / 256, 256>>>();
    // K5: normalize
    k5_norm<<<dim3(32, BT), 256>>>(out);
}